// round 13
// baseline (speedup 1.0000x reference)
#include <cuda_runtime.h>
#include <cstdint>
#include <math.h>

#define EPSI 1e-5f

typedef unsigned long long u64t;

__device__ __forceinline__ u64t splat2(float a) {
    u64t r; asm("mov.b64 %0, {%1, %1};" : "=l"(r) : "f"(a)); return r;
}
__device__ __forceinline__ void fma2(u64t& d, u64t a, u64t b) {
    asm("fma.rn.f32x2 %0, %1, %2, %0;" : "+l"(d) : "l"(a), "l"(b));
}
__device__ __forceinline__ void unpack2(u64t v, float& lo, float& hi) {
    asm("mov.b64 {%0, %1}, %2;" : "=f"(lo), "=f"(hi) : "l"(v));
}
__device__ __forceinline__ void cp16(unsigned int dst, const void* src) {
    asm volatile("cp.async.cg.shared.global [%0], [%1], 16;" :: "r"(dst), "l"(src));
}

__device__ __forceinline__ float f4c(const float4& v, int i) {
    switch (i & 3) {
        case 0: return v.x;
        case 1: return v.y;
        case 2: return v.z;
        default: return v.w;
    }
}

// Full-width block GEMM (accumulate-only): C[32x256] += A[32xKTOT] * W[KTOT x 256].
// 256 threads, 8 warps. Warp w owns cols [16w,+16) lo and [128+16w,+16) hi.
// Lane: rp=lane&3 -> 8 rows rp+4i; q=lane>>2 -> 4 CONTIGUOUS cols:
//   q<4: lo cols 16w+4q..+3 ; q>=4: hi cols 128+16w+4(q-4)..+3.
// W smem k-row = 32 floats [lo 16 | hi 16]; thread reads ONE LDS.128 at q*4.
// Per k: 16 FFMA2, 1 LDS.128 W (1 wavefront, was 2). GLU pairing done at
// epilogue via shfl_xor(16). Warp-private W double buffer, own cp.async groups,
// NO __syncthreads inside.
template <int KTOT>
__device__ __forceinline__ void gemm_tile_acc(
    const float* __restrict__ As, int lda,
    const float* __restrict__ Wg, int ldw,
    float* __restrict__ wbuf, u64t (&acc)[8][2])
{
    const int tid  = threadIdx.x;
    const int wid  = tid >> 5, lane = tid & 31;
    const int rp   = lane & 3, q = lane >> 2;
    constexpr int NCH = KTOT / 16;

    float* wb = wbuf + wid * 1024;
    const unsigned int wb_s = (unsigned int)__cvta_generic_to_shared(wb);
    const int seg0 = lane >> 2;
    const int part = lane & 3;

    auto load_chunk = [&](int ch, int stage) {
        const float* Wr = Wg + ch * 16 * ldw + wid * 16 + part * 4;
#pragma unroll
        for (int j = 0; j < 4; j++) {
            int seg = seg0 + 8 * j;
            int k = seg >> 1, half = seg & 1;
            cp16(wb_s + stage * 2048 + k * 128 + half * 64 + part * 16,
                 Wr + k * ldw + half * 128);
        }
        asm volatile("cp.async.commit_group;" ::: "memory");
    };

    load_chunk(0, 0);

    int cur = 0;
    for (int ch = 0; ch < NCH; ch++) {
        const bool more = (ch + 1 < NCH);
        if (more) {
            load_chunk(ch + 1, cur ^ 1);
            asm volatile("cp.async.wait_group 1;" ::: "memory");
        } else {
            asm volatile("cp.async.wait_group 0;" ::: "memory");
        }
        const float* wc = wb + cur * 512;
        const int kk = ch * 16;
#pragma unroll
        for (int k4 = 0; k4 < 4; k4++) {
            float4 a[8];
#pragma unroll
            for (int i = 0; i < 8; i++)
                a[i] = *reinterpret_cast<const float4*>(
                    As + (rp + 4 * i) * lda + kk + k4 * 4);
#pragma unroll
            for (int kz = 0; kz < 4; kz++) {
                ulonglong2 wv = *reinterpret_cast<const ulonglong2*>(
                    wc + (k4 * 4 + kz) * 32 + q * 4);
#pragma unroll
                for (int i = 0; i < 8; i++) {
                    u64t s = splat2(f4c(a[i], kz));
                    fma2(acc[i][0], s, wv.x);
                    fma2(acc[i][1], s, wv.y);
                }
            }
        }
        cur ^= 1;
    }
}

// Half-width block GEMM: live output cols {0..63} U {128..191} only.
// 8 warps = 2 row-groups x 4 col-groups. Warp (grp,w4): rows [16grp,+16),
// cols [16w4,+16) lo U [128+16w4,+16) hi. Same contiguous-4-col W scheme.
// Thread: 4 rows x 4 cols; per k: 8 FFMA2, 1 LDS.128 W.
template <int KTOT, typename Epi>
__device__ __forceinline__ void gemm_tile_half(
    const float* __restrict__ As, int lda,
    const float* __restrict__ Wg, int ldw,
    float* __restrict__ wbuf, Epi epi)
{
    const int tid  = threadIdx.x;
    const int wid  = tid >> 5, lane = tid & 31;
    const int w4   = wid & 3, grp = wid >> 2;
    const int rp   = lane & 3, q = lane >> 2;
    const int rbase = grp * 16 + rp;
    constexpr int NCH = KTOT / 16;

    float* wb = wbuf + wid * 1024;
    const unsigned int wb_s = (unsigned int)__cvta_generic_to_shared(wb);
    const int seg0 = lane >> 2;
    const int part = lane & 3;

    u64t acc[4][2];
#pragma unroll
    for (int i = 0; i < 4; i++) { acc[i][0] = 0ull; acc[i][1] = 0ull; }

    auto load_chunk = [&](int ch, int stage) {
        const float* Wr = Wg + ch * 16 * ldw + w4 * 16 + part * 4;
#pragma unroll
        for (int j = 0; j < 4; j++) {
            int seg = seg0 + 8 * j;
            int k = seg >> 1, half = seg & 1;
            cp16(wb_s + stage * 2048 + k * 128 + half * 64 + part * 16,
                 Wr + k * ldw + half * 128);
        }
        asm volatile("cp.async.commit_group;" ::: "memory");
    };

    load_chunk(0, 0);

    int cur = 0;
    for (int ch = 0; ch < NCH; ch++) {
        const bool more = (ch + 1 < NCH);
        if (more) {
            load_chunk(ch + 1, cur ^ 1);
            asm volatile("cp.async.wait_group 1;" ::: "memory");
        } else {
            asm volatile("cp.async.wait_group 0;" ::: "memory");
        }
        const float* wc = wb + cur * 512;
        const int kk = ch * 16;
#pragma unroll
        for (int k4 = 0; k4 < 4; k4++) {
            float4 a[4];
#pragma unroll
            for (int i = 0; i < 4; i++)
                a[i] = *reinterpret_cast<const float4*>(
                    As + (rbase + 4 * i) * lda + kk + k4 * 4);
#pragma unroll
            for (int kz = 0; kz < 4; kz++) {
                ulonglong2 wv = *reinterpret_cast<const ulonglong2*>(
                    wc + (k4 * 4 + kz) * 32 + q * 4);
#pragma unroll
                for (int i = 0; i < 4; i++) {
                    u64t s = splat2(f4c(a[i], kz));
                    fma2(acc[i][0], s, wv.x);
                    fma2(acc[i][1], s, wv.y);
                }
            }
        }
        cur ^= 1;
    }
    epi(rbase, acc);
}

#define XH_LD 260
#define SH_LD 132

__global__ __launch_bounds__(256, 2)
void tabnet_kernel(
    const float* __restrict__ x,
    const float* __restrict__ bn0_g, const float* __restrict__ bn0_b,
    const float* __restrict__ bn0_m, const float* __restrict__ bn0_v,
    const float* __restrict__ shW,
    const float* __restrict__ sh_g, const float* __restrict__ sh_b,
    const float* __restrict__ sh_m, const float* __restrict__ sh_v,
    const float* __restrict__ stW,
    const float* __restrict__ st_g, const float* __restrict__ st_b,
    const float* __restrict__ st_m, const float* __restrict__ st_v,
    const float* __restrict__ fW, const float* __restrict__ fb,
    float* __restrict__ out)
{
    extern __shared__ float smem[];
    float* xsh   = smem;             // [32][260] x K-half tile
    float* shb   = smem + 8320;      // [32][132] GLU(shared step) output
    float* aggs  = smem + 12544;     // [32][64]
    float* wbuf  = smem + 14592;     // 8 warps x 2 stages x 512
    float* bn0sc = smem + 22784;     // [512]
    float* bn0sh = smem + 23296;     // [512]
    float* sbnsc = smem + 23808;     // [256] shared/step bn tables
    float* sbnsh = smem + 24064;     // [256]
    // total 24320 floats = 97280 bytes -> 2 blocks/SM

    const int tid = threadIdx.x;
    const int row0 = blockIdx.x << 5;

    for (int c = tid; c < 512; c += 256) {
        float sc = bn0_g[c] * rsqrtf(bn0_v[c] + EPSI);
        bn0sc[c] = sc;
        bn0sh[c] = bn0_b[c] - bn0_m[c] * sc;
    }
    __syncthreads();

    // GEMM1 accumulators persist across the two K-halves
    u64t acc1[8][2];
#pragma unroll
    for (int i = 0; i < 8; i++) { acc1[i][0] = 0ull; acc1[i][1] = 0ull; }

    for (int h = 0; h < 2; h++) {
        if (h) __syncthreads();   // all warps done reading previous x half
        // load x half h (cols [256h, 256h+256)) + bn0
        {
            const float4* xg = reinterpret_cast<const float4*>(x)
                             + (size_t)row0 * 128 + h * 64;
            const float4* s4 = reinterpret_cast<const float4*>(bn0sc) + h * 64;
            const float4* b4 = reinterpret_cast<const float4*>(bn0sh) + h * 64;
            float4* xs4 = reinterpret_cast<float4*>(xsh);
#pragma unroll
            for (int i = 0; i < 8; i++) {
                int f = tid + 256 * i;
                int r = f >> 6, c4 = f & 63;
                float4 v = xg[r * 128 + c4];
                float4 s = s4[c4], b = b4[c4];
                v.x = fmaf(v.x, s.x, b.x);
                v.y = fmaf(v.y, s.y, b.y);
                v.z = fmaf(v.z, s.z, b.z);
                v.w = fmaf(v.w, s.w, b.w);
                xs4[r * 65 + c4] = v;
            }
        }
        if (h == 1) {
            // shared-step bn tables (needed only by the epilogue after half 2)
            int c = tid;
            float sc = sh_g[c] * rsqrtf(sh_v[c] + EPSI);
            sbnsc[c] = sc;
            sbnsh[c] = sh_b[c] - sh_m[c] * sc;
        }
        __syncthreads();
        gemm_tile_acc<256>(xsh, XH_LD, shW + h * 256 * 256, 256, wbuf, acc1);
    }

    // GEMM1 epilogue: sh = GLU(bn(.)); GLU pairing via shfl_xor(16).
    {
        const int wid = tid >> 5, lane = tid & 31;
        const int rp = lane & 3, q = lane >> 2;
        const int c0b = wid * 16 + (q & 3) * 4;
        const bool hib = q >= 4;
#pragma unroll
        for (int i = 0; i < 8; i++) {
            int row = rp + 4 * i;
            float v[4], bv[4], ov[4];
            unpack2(acc1[i][0], v[0], v[1]);
            unpack2(acc1[i][1], v[2], v[3]);
#pragma unroll
            for (int t = 0; t < 4; t++) {
                int col = (hib ? 128 : 0) + c0b + t;
                bv[t] = fmaf(v[t], sbnsc[col], sbnsh[col]);
            }
#pragma unroll
            for (int t = 0; t < 4; t++)
                ov[t] = __shfl_xor_sync(0xffffffffu, bv[t], 16);
            // lo lanes store rows i<4, hi lanes store rows i>=4
            if ((i >= 4) == hib) {
                float4 g;
                float u0 = hib ? ov[0] : bv[0], w0 = hib ? bv[0] : ov[0];
                float u1 = hib ? ov[1] : bv[1], w1 = hib ? bv[1] : ov[1];
                float u2 = hib ? ov[2] : bv[2], w2 = hib ? bv[2] : ov[2];
                float u3 = hib ? ov[3] : bv[3], w3 = hib ? bv[3] : ov[3];
                g.x = u0 / (1.f + __expf(-w0));
                g.y = u1 / (1.f + __expf(-w1));
                g.z = u2 / (1.f + __expf(-w2));
                g.w = u3 / (1.f + __expf(-w3));
                *reinterpret_cast<float4*>(shb + row * SH_LD + c0b) = g;
            }
        }
    }
    __syncthreads();

    // agg in registers: thread owns 2 rows x 4 cols
    // lo lanes: rows rbase+{0,4}; hi lanes: rows rbase+{8,12}
    float agg[2][4];
#pragma unroll
    for (int j = 0; j < 2; j++)
#pragma unroll
        for (int t = 0; t < 4; t++) agg[j][t] = 0.f;

    for (int s = 0; s < 3; s++) {
        {
            int c = tid;
            float sc = st_g[s * 256 + c] * rsqrtf(st_v[s * 256 + c] + EPSI);
            sbnsc[c] = sc;
            sbnsh[c] = st_b[s * 256 + c] - st_m[s * 256 + c] * sc;
        }
        __syncthreads();
        // GEMM2 (half): h_d = GLU(bn(sh @ stW[s]))[:, :64]; agg += h_d
        gemm_tile_half<128>(shb, SH_LD, stW + s * 128 * 256, 256, wbuf,
            [&](int rb, u64t (&acc)[4][2]) {
                const int lane = tid & 31;
                const int q = lane >> 2;
                const int w4 = (tid >> 5) & 3;
                const int c0b = w4 * 16 + (q & 3) * 4;
                const bool hib = q >= 4;
#pragma unroll
                for (int i = 0; i < 4; i++) {
                    float v[4], bv[4], ov[4];
                    unpack2(acc[i][0], v[0], v[1]);
                    unpack2(acc[i][1], v[2], v[3]);
#pragma unroll
                    for (int t = 0; t < 4; t++) {
                        int col = (hib ? 128 : 0) + c0b + t;
                        bv[t] = fmaf(v[t], sbnsc[col], sbnsh[col]);
                    }
#pragma unroll
                    for (int t = 0; t < 4; t++)
                        ov[t] = __shfl_xor_sync(0xffffffffu, bv[t], 16);
                    // lo lanes own i=0,1 ; hi lanes own i=2,3
                    if ((i >= 2) == hib) {
                        int j = hib ? (i - 2) : i;
#pragma unroll
                        for (int t = 0; t < 4; t++) {
                            float u = hib ? ov[t] : bv[t];
                            float w = hib ? bv[t] : ov[t];
                            agg[j][t] += u / (1.f + __expf(-w));
                        }
                    }
                }
            });
        __syncthreads();
    }

    // write agg registers to smem (lo: rows rbase+{0,4}; hi: rbase+{8,12})
    {
        const int wid = tid >> 5, lane = tid & 31;
        const int w4 = wid & 3, grp = wid >> 2;
        const int rp = lane & 3, q = lane >> 2;
        const int c0b = w4 * 16 + (q & 3) * 4;
        const bool hib = q >= 4;
        const int rb = grp * 16 + rp + (hib ? 8 : 0);
#pragma unroll
        for (int j = 0; j < 2; j++) {
            float4 g = make_float4(agg[j][0], agg[j][1], agg[j][2], agg[j][3]);
            *reinterpret_cast<float4*>(aggs + (rb + 4 * j) * 64 + c0b) = g;
        }
    }
    __syncthreads();

    // final: out = agg @ fW + fb
    if (tid < 64) {
        int m = tid >> 1, o = tid & 1;
        float acc = fb[o];
#pragma unroll
        for (int j = 0; j < 64; j++) acc = fmaf(aggs[m * 64 + j], fW[j * 2 + o], acc);
        out[(size_t)(row0 + m) * 2 + o] = acc;
    }
}

extern "C" void kernel_launch(void* const* d_in, const int* in_sizes, int n_in,
                              void* d_out, int out_size)
{
    const float* x    = (const float*)d_in[0];
    const float* bn0g = (const float*)d_in[1];
    const float* bn0b = (const float*)d_in[2];
    const float* bn0m = (const float*)d_in[3];
    const float* bn0v = (const float*)d_in[4];
    const float* shW  = (const float*)d_in[5];
    const float* shg  = (const float*)d_in[6];
    const float* shbp = (const float*)d_in[7];
    const float* shm  = (const float*)d_in[8];
    const float* shv  = (const float*)d_in[9];
    const float* stW  = (const float*)d_in[10];
    const float* stg  = (const float*)d_in[11];
    const float* stb  = (const float*)d_in[12];
    const float* stm  = (const float*)d_in[13];
    const float* stv  = (const float*)d_in[14];
    const float* fW   = (const float*)d_in[20];
    const float* fb   = (const float*)d_in[21];

    int Btot = in_sizes[0] / 512;
    int grid = Btot / 32;
    size_t smem = 24320 * sizeof(float);
    cudaFuncSetAttribute(tabnet_kernel,
                         cudaFuncAttributeMaxDynamicSharedMemorySize, (int)smem);
    tabnet_kernel<<<grid, 256, smem>>>(
        x, bn0g, bn0b, bn0m, bn0v,
        shW, shg, shbp, shm, shv,
        stW, stg, stb, stm, stv,
        fW, fb, (float*)d_out);
}